// round 1
// baseline (speedup 1.0000x reference)
#include <cuda_runtime.h>
#include <cstdint>

// Problem constants
#define NN 100000
#define EE 1600000
#define HH 4
#define DD 32
#define EFF 32
#define NT 4
#define ET 8
#define HD 128           // H*D
#define NEG_SLOPE 0.2f

// Scratch (static device allocations — allowed)
__device__ float g_fs[NN * HD];       // feat * fc[node_type]   (51.2 MB)
__device__ float g_ex[EE * HH];       // exp(leaky_relu(score)) (25.6 MB)
__device__ float g_el[NN * HH];       // left attention logits
__device__ float g_er[NN * HH];       // right attention logits
__device__ float g_s [NN * HH];       // softmax denominators
__device__ float g_ee[ET * HH];       // per-edge-type scores

// ---------------------------------------------------------------------------
// Kernel 0: edge-type embedding path. ee[t,h] = sum_f attn_e[h,f] *
//           (sum_g edge_emb[t,g] * W_e[h*EF+f, g])
// ---------------------------------------------------------------------------
__global__ void k_ee(const float* __restrict__ edge_emb,
                     const float* __restrict__ W_e,
                     const float* __restrict__ attn_e) {
    int t = threadIdx.x;          // 0..31 => (et, h)
    if (t >= ET * HH) return;
    int et = t >> 2;
    int h  = t & 3;
    float acc = 0.f;
    #pragma unroll 4
    for (int f = 0; f < EFF; f++) {
        const float* w = W_e + (h * EFF + f) * EFF;
        float emb = 0.f;
        #pragma unroll
        for (int g = 0; g < EFF; g++)
            emb += edge_emb[et * EFF + g] * w[g];
        acc += attn_e[h * EFF + f] * emb;
    }
    g_ee[et * HH + h] = acc;
}

// ---------------------------------------------------------------------------
// Kernel 1: per-node. One warp per node (128 floats -> lane holds float4).
//   fs = feat * fc[nt]; el = fs . attn_l (per head); er = fs . attn_r
//   rst initialized to feat (residual). Also zeros g_s.
// ---------------------------------------------------------------------------
__global__ void k_node(const float* __restrict__ feat,
                       const float* __restrict__ fc,
                       const float* __restrict__ attn_l,
                       const float* __restrict__ attn_r,
                       const int*   __restrict__ node_types,
                       float*       __restrict__ rst) {
    int warp = (blockIdx.x * blockDim.x + threadIdx.x) >> 5;
    int lane = threadIdx.x & 31;
    if (warp >= NN) return;

    int nt = node_types[warp];
    float4 f  = ((const float4*)(feat + (size_t)warp * HD))[lane];
    float4 c  = ((const float4*)(fc   + nt * HD))[lane];
    float4 fs = make_float4(f.x * c.x, f.y * c.y, f.z * c.z, f.w * c.w);

    ((float4*)(g_fs + (size_t)warp * HD))[lane] = fs;
    ((float4*)(rst  + (size_t)warp * HD))[lane] = f;   // residual init

    float4 al = ((const float4*)attn_l)[lane];
    float4 ar = ((const float4*)attn_r)[lane];
    float el = fs.x * al.x + fs.y * al.y + fs.z * al.z + fs.w * al.w;
    float er = fs.x * ar.x + fs.y * ar.y + fs.z * ar.z + fs.w * ar.w;

    // segmented reduction across groups of 8 lanes (one head per group)
    #pragma unroll
    for (int off = 4; off >= 1; off >>= 1) {
        el += __shfl_down_sync(0xffffffffu, el, off);
        er += __shfl_down_sync(0xffffffffu, er, off);
    }
    int h = lane >> 3;
    if ((lane & 7) == 0) {
        g_el[warp * HH + h] = el;
        g_er[warp * HH + h] = er;
    }
    if (lane < HH) g_s[warp * HH + lane] = 0.f;
}

// ---------------------------------------------------------------------------
// Kernel 2: per-edge scores. One thread per edge, all 4 heads as float4.
//   score = leaky_relu(el[src] + er[dst] + ee[etype]); ex = exp(score)
//   (segment-max subtraction skipped: ratio identical, scores are O(0.1))
//   Accumulate softmax denominator into g_s[dst] via vector reduction.
// ---------------------------------------------------------------------------
__global__ void k_score(const int* __restrict__ src,
                        const int* __restrict__ dst,
                        const int* __restrict__ e_feat) {
    int e = blockIdx.x * blockDim.x + threadIdx.x;
    if (e >= EE) return;
    int s = src[e], d = dst[e], t = e_feat[e];

    float4 el = ((const float4*)g_el)[s];
    float4 er = ((const float4*)g_er)[d];
    float4 ee = ((const float4*)g_ee)[t];

    float v0 = el.x + er.x + ee.x;
    float v1 = el.y + er.y + ee.y;
    float v2 = el.z + er.z + ee.z;
    float v3 = el.w + er.w + ee.w;
    v0 = v0 > 0.f ? v0 : NEG_SLOPE * v0;
    v1 = v1 > 0.f ? v1 : NEG_SLOPE * v1;
    v2 = v2 > 0.f ? v2 : NEG_SLOPE * v2;
    v3 = v3 > 0.f ? v3 : NEG_SLOPE * v3;

    float4 ex = make_float4(__expf(v0), __expf(v1), __expf(v2), __expf(v3));
    ((float4*)g_ex)[e] = ex;

    float* sp = g_s + d * HH;
    asm volatile("red.global.add.v4.f32 [%0], {%1, %2, %3, %4};"
                 :: "l"(sp), "f"(ex.x), "f"(ex.y), "f"(ex.z), "f"(ex.w)
                 : "memory");
}

// ---------------------------------------------------------------------------
// Kernel 3: aggregation. One warp per edge.
//   a = ex / s[dst]; out_a written by one lane per head.
//   rst[dst] += fs[src] * a  via red.global.add.v4.f32 (lane-per-float4).
// ---------------------------------------------------------------------------
__global__ void k_agg(const int* __restrict__ src,
                      const int* __restrict__ dst,
                      float*     __restrict__ out) {
    int warp = (blockIdx.x * blockDim.x + threadIdx.x) >> 5;
    int lane = threadIdx.x & 31;
    if (warp >= EE) return;

    int s = src[warp], d = dst[warp];
    int h = lane >> 3;

    float ex = g_ex[(size_t)warp * HH + h];   // broadcast within group of 8
    float sv = g_s[d * HH + h];
    float a  = ex / sv;

    if ((lane & 7) == 0)
        out[(size_t)NN * HD + (size_t)warp * HH + h] = a;

    float4 fs = ((const float4*)(g_fs + (size_t)s * HD))[lane];
    float* op = out + (size_t)d * HD + lane * 4;
    asm volatile("red.global.add.v4.f32 [%0], {%1, %2, %3, %4};"
                 :: "l"(op), "f"(fs.x * a), "f"(fs.y * a), "f"(fs.z * a), "f"(fs.w * a)
                 : "memory");
}

// ---------------------------------------------------------------------------
extern "C" void kernel_launch(void* const* d_in, const int* in_sizes, int n_in,
                              void* d_out, int out_size) {
    const float* feat       = (const float*)d_in[0];
    const float* fc         = (const float*)d_in[1];
    const float* edge_emb   = (const float*)d_in[2];
    const float* W_e        = (const float*)d_in[3];
    const float* attn_l     = (const float*)d_in[4];
    const float* attn_r     = (const float*)d_in[5];
    const float* attn_e     = (const float*)d_in[6];
    const int*   node_types = (const int*)d_in[7];
    const int*   e_feat     = (const int*)d_in[8];
    const int*   src        = (const int*)d_in[9];
    const int*   dst        = (const int*)d_in[10];
    float* out = (float*)d_out;

    k_ee<<<1, 32>>>(edge_emb, W_e, attn_e);

    // one warp per node
    int node_blocks = (NN + 7) / 8;            // 8 warps / 256-thread block
    k_node<<<node_blocks, 256>>>(feat, fc, attn_l, attn_r, node_types, out);

    int score_blocks = (EE + 255) / 256;
    k_score<<<score_blocks, 256>>>(src, dst, e_feat);

    // one warp per edge
    int agg_blocks = (EE + 7) / 8;
    k_agg<<<agg_blocks, 256>>>(src, dst, out);
}

// round 2
// speedup vs baseline: 1.3596x; 1.3596x over previous
#include <cuda_runtime.h>
#include <cstdint>

// Problem constants
#define NN 100000
#define EE 1600000
#define HH 4
#define DD 32
#define EFF 32
#define ET 8
#define HD 128           // H*D
#define NEG_SLOPE 0.2f

// Scratch (static device allocations — allowed)
__device__ float g_fs[NN * HD];        // feat * fc[node_type]   (51.2 MB)
__device__ float g_ex[EE * HH];        // exp(leaky_relu(score)) (25.6 MB)
__device__ float g_el[NN * HH];        // left attention logits
__device__ float g_er[NN * HH];        // right attention logits
__device__ float g_s [NN * HH];        // softmax denominators
__device__ float g_ee[ET * HH];        // per-edge-type scores
__device__ int   g_deg[NN];            // dst degree histogram
__device__ int   g_rowptr[NN + 1];     // CSR row pointers
__device__ int   g_cursor[NN];         // scatter cursors
__device__ int   g_srcs[EE];           // src, dst-sorted           (6.4 MB)
__device__ float g_asrt[EE * HH];      // a = ex/s, dst-sorted      (25.6 MB)

// ---------------------------------------------------------------------------
// Kernel 0: edge-type embedding path.
// ---------------------------------------------------------------------------
__global__ void k_ee(const float* __restrict__ edge_emb,
                     const float* __restrict__ W_e,
                     const float* __restrict__ attn_e) {
    int t = threadIdx.x;
    if (t >= ET * HH) return;
    int et = t >> 2;
    int h  = t & 3;
    float acc = 0.f;
    for (int f = 0; f < EFF; f++) {
        const float* w = W_e + (h * EFF + f) * EFF;
        float emb = 0.f;
        #pragma unroll
        for (int g = 0; g < EFF; g++)
            emb += edge_emb[et * EFF + g] * w[g];
        acc += attn_e[h * EFF + f] * emb;
    }
    g_ee[et * HH + h] = acc;
}

// ---------------------------------------------------------------------------
// Kernel 1: per-node. One warp per node.
//   fs = feat * fc[nt]; el/er per-head dots. Zero g_s and g_deg.
// ---------------------------------------------------------------------------
__global__ void k_node(const float* __restrict__ feat,
                       const float* __restrict__ fc,
                       const float* __restrict__ attn_l,
                       const float* __restrict__ attn_r,
                       const int*   __restrict__ node_types) {
    int warp = (blockIdx.x * blockDim.x + threadIdx.x) >> 5;
    int lane = threadIdx.x & 31;
    if (warp >= NN) return;

    int nt = node_types[warp];
    float4 f  = ((const float4*)(feat + (size_t)warp * HD))[lane];
    float4 c  = ((const float4*)(fc   + nt * HD))[lane];
    float4 fs = make_float4(f.x * c.x, f.y * c.y, f.z * c.z, f.w * c.w);

    ((float4*)(g_fs + (size_t)warp * HD))[lane] = fs;

    float4 al = ((const float4*)attn_l)[lane];
    float4 ar = ((const float4*)attn_r)[lane];
    float el = fs.x * al.x + fs.y * al.y + fs.z * al.z + fs.w * al.w;
    float er = fs.x * ar.x + fs.y * ar.y + fs.z * ar.z + fs.w * ar.w;

    #pragma unroll
    for (int off = 4; off >= 1; off >>= 1) {
        el += __shfl_down_sync(0xffffffffu, el, off);
        er += __shfl_down_sync(0xffffffffu, er, off);
    }
    int h = lane >> 3;
    if ((lane & 7) == 0) {
        g_el[warp * HH + h] = el;
        g_er[warp * HH + h] = er;
    }
    if (lane < HH) g_s[warp * HH + lane] = 0.f;
    if (lane == 4) g_deg[warp] = 0;
}

// ---------------------------------------------------------------------------
// Kernel 2: per-edge scores + dst histogram. One thread per edge.
//   ex = exp(leaky_relu(el[src]+er[dst]+ee[etype])); red into g_s[dst];
//   atomicAdd dst degree. (segment-max skipped: ratio identical, scores tiny)
// ---------------------------------------------------------------------------
__global__ void k_score(const int* __restrict__ src,
                        const int* __restrict__ dst,
                        const int* __restrict__ e_feat) {
    int e = blockIdx.x * blockDim.x + threadIdx.x;
    if (e >= EE) return;
    int s = src[e], d = dst[e], t = e_feat[e];

    float4 el = ((const float4*)g_el)[s];
    float4 er = ((const float4*)g_er)[d];
    float4 ee = ((const float4*)g_ee)[t];

    float v0 = el.x + er.x + ee.x;
    float v1 = el.y + er.y + ee.y;
    float v2 = el.z + er.z + ee.z;
    float v3 = el.w + er.w + ee.w;
    v0 = v0 > 0.f ? v0 : NEG_SLOPE * v0;
    v1 = v1 > 0.f ? v1 : NEG_SLOPE * v1;
    v2 = v2 > 0.f ? v2 : NEG_SLOPE * v2;
    v3 = v3 > 0.f ? v3 : NEG_SLOPE * v3;

    float4 ex = make_float4(__expf(v0), __expf(v1), __expf(v2), __expf(v3));
    ((float4*)g_ex)[e] = ex;

    float* sp = g_s + d * HH;
    asm volatile("red.global.add.v4.f32 [%0], {%1, %2, %3, %4};"
                 :: "l"(sp), "f"(ex.x), "f"(ex.y), "f"(ex.z), "f"(ex.w)
                 : "memory");
    atomicAdd(&g_deg[d], 1);
}

// ---------------------------------------------------------------------------
// Kernel 3: single-block exclusive scan of g_deg -> g_rowptr, g_cursor.
// ---------------------------------------------------------------------------
__global__ void k_scan() {
    __shared__ int warp_sums[32];
    __shared__ int s_carry;
    int tid = threadIdx.x, lane = tid & 31, wid = tid >> 5;
    if (tid == 0) s_carry = 0;
    __syncthreads();
    for (int base = 0; base < NN; base += 1024) {
        int i = base + tid;
        int v = (i < NN) ? g_deg[i] : 0;
        int x = v;
        #pragma unroll
        for (int off = 1; off < 32; off <<= 1) {
            int y = __shfl_up_sync(0xffffffffu, x, off);
            if (lane >= off) x += y;
        }
        if (lane == 31) warp_sums[wid] = x;
        __syncthreads();
        if (wid == 0) {
            int w = warp_sums[lane];
            #pragma unroll
            for (int off = 1; off < 32; off <<= 1) {
                int y = __shfl_up_sync(0xffffffffu, w, off);
                if (lane >= off) w += y;
            }
            warp_sums[lane] = w;
        }
        __syncthreads();
        int excl = s_carry + (wid ? warp_sums[wid - 1] : 0) + x - v;
        if (i < NN) { g_rowptr[i] = excl; g_cursor[i] = excl; }
        __syncthreads();
        if (tid == 0) s_carry += warp_sums[31];
        __syncthreads();
    }
    if (threadIdx.x == 0) g_rowptr[NN] = s_carry;
}

// ---------------------------------------------------------------------------
// Kernel 4: scatter edges into dst-sorted order. One thread per edge.
//   a = ex/s[dst]; write a to out (coalesced in e) and to the sorted arrays.
// ---------------------------------------------------------------------------
__global__ void k_scatter(const int* __restrict__ src,
                          const int* __restrict__ dst,
                          float* __restrict__ out) {
    int e = blockIdx.x * blockDim.x + threadIdx.x;
    if (e >= EE) return;
    int s = src[e], d = dst[e];

    float4 ex = ((const float4*)g_ex)[e];
    float4 sv = ((const float4*)g_s)[d];
    float4 a  = make_float4(ex.x / sv.x, ex.y / sv.y, ex.z / sv.z, ex.w / sv.w);

    ((float4*)(out + (size_t)NN * HD))[e] = a;     // a output, coalesced

    int pos = atomicAdd(&g_cursor[d], 1);
    g_srcs[pos] = s;
    ((float4*)g_asrt)[pos] = a;
}

// ---------------------------------------------------------------------------
// Kernel 5: gather-side aggregation. One warp per dst node; atomic-free.
//   out[d] = feat[d] + sum_{e in row(d)} fs[src_e] * a_e
// ---------------------------------------------------------------------------
__global__ void __launch_bounds__(256) k_agg(const float* __restrict__ feat,
                                             float* __restrict__ out) {
    int warp = (blockIdx.x * blockDim.x + threadIdx.x) >> 5;
    int lane = threadIdx.x & 31;
    if (warp >= NN) return;

    int beg = g_rowptr[warp];
    int end = g_rowptr[warp + 1];
    int h = lane >> 3;

    float accx = 0.f, accy = 0.f, accz = 0.f, accw = 0.f;
    #pragma unroll 4
    for (int j = beg; j < end; j++) {
        int   s = __ldg(&g_srcs[j]);
        float a = __ldg(&g_asrt[j * HH + h]);
        float4 fs = __ldg((const float4*)(g_fs + (size_t)s * HD) + lane);
        accx += fs.x * a;
        accy += fs.y * a;
        accz += fs.z * a;
        accw += fs.w * a;
    }

    float4 f = ((const float4*)(feat + (size_t)warp * HD))[lane];
    float4 r = make_float4(f.x + accx, f.y + accy, f.z + accz, f.w + accw);
    ((float4*)(out + (size_t)warp * HD))[lane] = r;
}

// ---------------------------------------------------------------------------
extern "C" void kernel_launch(void* const* d_in, const int* in_sizes, int n_in,
                              void* d_out, int out_size) {
    const float* feat       = (const float*)d_in[0];
    const float* fc         = (const float*)d_in[1];
    const float* edge_emb   = (const float*)d_in[2];
    const float* W_e        = (const float*)d_in[3];
    const float* attn_l     = (const float*)d_in[4];
    const float* attn_r     = (const float*)d_in[5];
    const float* attn_e     = (const float*)d_in[6];
    const int*   node_types = (const int*)d_in[7];
    const int*   e_feat     = (const int*)d_in[8];
    const int*   src        = (const int*)d_in[9];
    const int*   dst        = (const int*)d_in[10];
    float* out = (float*)d_out;

    k_ee<<<1, 32>>>(edge_emb, W_e, attn_e);

    int node_blocks = (NN + 7) / 8;            // warp per node, 256-thread blocks
    k_node<<<node_blocks, 256>>>(feat, fc, attn_l, attn_r, node_types);

    int score_blocks = (EE + 255) / 256;
    k_score<<<score_blocks, 256>>>(src, dst, e_feat);

    k_scan<<<1, 1024>>>();

    k_scatter<<<score_blocks, 256>>>(src, dst, out);

    int agg_blocks = (NN + 7) / 8;             // warp per dst node
    k_agg<<<agg_blocks, 256>>>(feat, out);
}

// round 3
// speedup vs baseline: 1.7616x; 1.2956x over previous
#include <cuda_runtime.h>
#include <cstdint>

// Problem constants
#define NN 100000
#define EE 1600000
#define HH 4
#define DD 32
#define EFF 32
#define ET 8
#define HD 128           // H*D
#define NEG_SLOPE 0.2f

#define SCAN_BLK 1024
#define SCAN_NB  ((NN + SCAN_BLK - 1) / SCAN_BLK)   // 98

// Scratch (static device allocations — allowed)
__device__ float g_fs[NN * HD];        // feat * fc[node_type]   (51.2 MB)
__device__ float g_ex[EE * HH];        // exp(leaky_relu(score)) (25.6 MB)
__device__ float g_el[NN * HH];        // left attention logits
__device__ float g_er[NN * HH];        // right attention logits
__device__ float g_s [NN * HH];        // softmax denominators
__device__ float g_ee[ET * HH];        // per-edge-type scores
__device__ int   g_deg[NN];            // dst degree histogram
__device__ int   g_rowptr[NN + 1];     // CSR row pointers
__device__ int   g_cursor[NN];         // scatter cursors
__device__ int   g_bsum[SCAN_NB];      // per-block scan totals
__device__ int   g_boff[SCAN_NB];      // per-block exclusive offsets
__device__ int   g_srcs[EE];           // src, dst-sorted           (6.4 MB)
__device__ float g_asrt[EE * HH];      // a = ex/s, dst-sorted      (25.6 MB)

// ---------------------------------------------------------------------------
// Kernel 0: edge-type embedding path.
// ---------------------------------------------------------------------------
__global__ void k_ee(const float* __restrict__ edge_emb,
                     const float* __restrict__ W_e,
                     const float* __restrict__ attn_e) {
    int t = threadIdx.x;
    if (t >= ET * HH) return;
    int et = t >> 2;
    int h  = t & 3;
    float acc = 0.f;
    for (int f = 0; f < EFF; f++) {
        const float* w = W_e + (h * EFF + f) * EFF;
        float emb = 0.f;
        #pragma unroll
        for (int g = 0; g < EFF; g++)
            emb += edge_emb[et * EFF + g] * w[g];
        acc += attn_e[h * EFF + f] * emb;
    }
    g_ee[et * HH + h] = acc;
}

// ---------------------------------------------------------------------------
// Kernel 1: per-node. One warp per node.
// ---------------------------------------------------------------------------
__global__ void k_node(const float* __restrict__ feat,
                       const float* __restrict__ fc,
                       const float* __restrict__ attn_l,
                       const float* __restrict__ attn_r,
                       const int*   __restrict__ node_types) {
    int warp = (blockIdx.x * blockDim.x + threadIdx.x) >> 5;
    int lane = threadIdx.x & 31;
    if (warp >= NN) return;

    int nt = node_types[warp];
    float4 f  = ((const float4*)(feat + (size_t)warp * HD))[lane];
    float4 c  = ((const float4*)(fc   + nt * HD))[lane];
    float4 fs = make_float4(f.x * c.x, f.y * c.y, f.z * c.z, f.w * c.w);

    ((float4*)(g_fs + (size_t)warp * HD))[lane] = fs;

    float4 al = ((const float4*)attn_l)[lane];
    float4 ar = ((const float4*)attn_r)[lane];
    float el = fs.x * al.x + fs.y * al.y + fs.z * al.z + fs.w * al.w;
    float er = fs.x * ar.x + fs.y * ar.y + fs.z * ar.z + fs.w * ar.w;

    #pragma unroll
    for (int off = 4; off >= 1; off >>= 1) {
        el += __shfl_down_sync(0xffffffffu, el, off);
        er += __shfl_down_sync(0xffffffffu, er, off);
    }
    int h = lane >> 3;
    if ((lane & 7) == 0) {
        g_el[warp * HH + h] = el;
        g_er[warp * HH + h] = er;
    }
    if (lane < HH) g_s[warp * HH + lane] = 0.f;
    if (lane == 4) g_deg[warp] = 0;
}

// ---------------------------------------------------------------------------
// Kernel 2: per-edge scores + dst histogram. One thread per edge.
// ---------------------------------------------------------------------------
__global__ void k_score(const int* __restrict__ src,
                        const int* __restrict__ dst,
                        const int* __restrict__ e_feat) {
    int e = blockIdx.x * blockDim.x + threadIdx.x;
    if (e >= EE) return;
    int s = src[e], d = dst[e], t = e_feat[e];

    float4 el = ((const float4*)g_el)[s];
    float4 er = ((const float4*)g_er)[d];
    float4 ee = ((const float4*)g_ee)[t];

    float v0 = el.x + er.x + ee.x;
    float v1 = el.y + er.y + ee.y;
    float v2 = el.z + er.z + ee.z;
    float v3 = el.w + er.w + ee.w;
    v0 = v0 > 0.f ? v0 : NEG_SLOPE * v0;
    v1 = v1 > 0.f ? v1 : NEG_SLOPE * v1;
    v2 = v2 > 0.f ? v2 : NEG_SLOPE * v2;
    v3 = v3 > 0.f ? v3 : NEG_SLOPE * v3;

    float4 ex = make_float4(__expf(v0), __expf(v1), __expf(v2), __expf(v3));
    ((float4*)g_ex)[e] = ex;

    float* sp = g_s + d * HH;
    asm volatile("red.global.add.v4.f32 [%0], {%1, %2, %3, %4};"
                 :: "l"(sp), "f"(ex.x), "f"(ex.y), "f"(ex.z), "f"(ex.w)
                 : "memory");
    atomicAdd(&g_deg[d], 1);
}

// ---------------------------------------------------------------------------
// Kernel 3a: per-block exclusive scan of g_deg. Writes local scan into
//            g_rowptr and block totals into g_bsum.
// ---------------------------------------------------------------------------
__global__ void k_scan_local() {
    __shared__ int warp_sums[32];
    int tid = threadIdx.x, lane = tid & 31, wid = tid >> 5;
    int i = blockIdx.x * SCAN_BLK + tid;
    int v = (i < NN) ? g_deg[i] : 0;
    int x = v;
    #pragma unroll
    for (int off = 1; off < 32; off <<= 1) {
        int y = __shfl_up_sync(0xffffffffu, x, off);
        if (lane >= off) x += y;
    }
    if (lane == 31) warp_sums[wid] = x;
    __syncthreads();
    if (wid == 0) {
        int w = warp_sums[lane];
        #pragma unroll
        for (int off = 1; off < 32; off <<= 1) {
            int y = __shfl_up_sync(0xffffffffu, w, off);
            if (lane >= off) w += y;
        }
        warp_sums[lane] = w;
    }
    __syncthreads();
    int excl = (wid ? warp_sums[wid - 1] : 0) + x - v;
    if (i < NN) g_rowptr[i] = excl;
    if (tid == SCAN_BLK - 1) g_bsum[blockIdx.x] = excl + v;
}

// ---------------------------------------------------------------------------
// Kernel 3b: scan the SCAN_NB block totals (single small block).
// ---------------------------------------------------------------------------
__global__ void k_scan_bsum() {
    __shared__ int warp_sums[4];
    int tid = threadIdx.x, lane = tid & 31, wid = tid >> 5;   // 128 threads
    int v = (tid < SCAN_NB) ? g_bsum[tid] : 0;
    int x = v;
    #pragma unroll
    for (int off = 1; off < 32; off <<= 1) {
        int y = __shfl_up_sync(0xffffffffu, x, off);
        if (lane >= off) x += y;
    }
    if (lane == 31) warp_sums[wid] = x;
    __syncthreads();
    int carry = 0;
    for (int w = 0; w < wid; w++) carry += warp_sums[w];
    if (tid < SCAN_NB) g_boff[tid] = carry + x - v;
    if (tid == SCAN_NB - 1) g_rowptr[NN] = carry + x;
}

// ---------------------------------------------------------------------------
// Kernel 3c: add block offsets; init cursors.
// ---------------------------------------------------------------------------
__global__ void k_scan_add() {
    int i = blockIdx.x * SCAN_BLK + threadIdx.x;
    if (i >= NN) return;
    int r = g_rowptr[i] + g_boff[blockIdx.x];
    g_rowptr[i] = r;
    g_cursor[i] = r;
}

// ---------------------------------------------------------------------------
// Kernel 4: scatter edges into dst-sorted order. One thread per edge.
// ---------------------------------------------------------------------------
__global__ void k_scatter(const int* __restrict__ src,
                          const int* __restrict__ dst,
                          float* __restrict__ out) {
    int e = blockIdx.x * blockDim.x + threadIdx.x;
    if (e >= EE) return;
    int s = src[e], d = dst[e];

    float4 ex = ((const float4*)g_ex)[e];
    float4 sv = ((const float4*)g_s)[d];
    float4 a  = make_float4(ex.x / sv.x, ex.y / sv.y, ex.z / sv.z, ex.w / sv.w);

    ((float4*)(out + (size_t)NN * HD))[e] = a;     // a output, coalesced

    int pos = atomicAdd(&g_cursor[d], 1);
    g_srcs[pos] = s;
    ((float4*)g_asrt)[pos] = a;
}

// ---------------------------------------------------------------------------
// Kernel 5: gather-side aggregation. One warp per dst node; atomic-free.
// ---------------------------------------------------------------------------
__global__ void __launch_bounds__(256) k_agg(const float* __restrict__ feat,
                                             float* __restrict__ out) {
    int warp = (blockIdx.x * blockDim.x + threadIdx.x) >> 5;
    int lane = threadIdx.x & 31;
    if (warp >= NN) return;

    int beg = g_rowptr[warp];
    int end = g_rowptr[warp + 1];
    int h = lane >> 3;

    float accx = 0.f, accy = 0.f, accz = 0.f, accw = 0.f;
    #pragma unroll 4
    for (int j = beg; j < end; j++) {
        int   s = __ldg(&g_srcs[j]);
        float a = __ldg(&g_asrt[j * HH + h]);
        float4 fs = __ldg((const float4*)(g_fs + (size_t)s * HD) + lane);
        accx += fs.x * a;
        accy += fs.y * a;
        accz += fs.z * a;
        accw += fs.w * a;
    }

    float4 f = ((const float4*)(feat + (size_t)warp * HD))[lane];
    float4 r = make_float4(f.x + accx, f.y + accy, f.z + accz, f.w + accw);
    ((float4*)(out + (size_t)warp * HD))[lane] = r;
}

// ---------------------------------------------------------------------------
extern "C" void kernel_launch(void* const* d_in, const int* in_sizes, int n_in,
                              void* d_out, int out_size) {
    const float* feat       = (const float*)d_in[0];
    const float* fc         = (const float*)d_in[1];
    const float* edge_emb   = (const float*)d_in[2];
    const float* W_e        = (const float*)d_in[3];
    const float* attn_l     = (const float*)d_in[4];
    const float* attn_r     = (const float*)d_in[5];
    const float* attn_e     = (const float*)d_in[6];
    const int*   node_types = (const int*)d_in[7];
    const int*   e_feat     = (const int*)d_in[8];
    const int*   src        = (const int*)d_in[9];
    const int*   dst        = (const int*)d_in[10];
    float* out = (float*)d_out;

    k_ee<<<1, 32>>>(edge_emb, W_e, attn_e);

    int node_blocks = (NN + 7) / 8;            // warp per node
    k_node<<<node_blocks, 256>>>(feat, fc, attn_l, attn_r, node_types);

    int score_blocks = (EE + 255) / 256;
    k_score<<<score_blocks, 256>>>(src, dst, e_feat);

    k_scan_local<<<SCAN_NB, SCAN_BLK>>>();
    k_scan_bsum<<<1, 128>>>();
    k_scan_add<<<SCAN_NB, SCAN_BLK>>>();

    k_scatter<<<score_blocks, 256>>>(src, dst, out);

    int agg_blocks = (NN + 7) / 8;             // warp per dst node
    k_agg<<<agg_blocks, 256>>>(feat, out);
}

// round 4
// speedup vs baseline: 1.9093x; 1.0838x over previous
#include <cuda_runtime.h>
#include <cuda_bf16.h>
#include <cstdint>

// Problem constants
#define NN 100000
#define EE 1600000
#define HH 4
#define DD 32
#define EFF 32
#define ET 8
#define HD 128           // H*D
#define NEG_SLOPE 0.2f

#define SCAN_BLK 1024
#define SCAN_NB  ((NN + SCAN_BLK - 1) / SCAN_BLK)   // 98

// Scratch (static device allocations — allowed)
__device__ __nv_bfloat16 g_fsh[NN * HD];  // feat*fc in bf16   (25.6 MB)
__device__ float g_ex[EE * HH];        // exp(leaky_relu(score)) (25.6 MB)
__device__ float g_el[NN * HH];        // left attention logits
__device__ float g_er[NN * HH];        // right attention logits
__device__ float g_s [NN * HH];        // softmax denominators
__device__ float g_ee[ET * HH];        // per-edge-type scores
__device__ int   g_deg[NN];            // dst degree histogram
__device__ int   g_rowptr[NN + 1];     // CSR row pointers
__device__ int   g_cursor[NN];         // scatter cursors
__device__ int   g_bsum[SCAN_NB];      // per-block scan totals
__device__ int   g_boff[SCAN_NB];      // per-block exclusive offsets
__device__ int   g_srcs[EE];           // src, dst-sorted           (6.4 MB)
__device__ float g_asrt[EE * HH];      // a = ex/s, dst-sorted      (25.6 MB)

// ---------------------------------------------------------------------------
// Kernel 0: edge-type embedding path.
// ---------------------------------------------------------------------------
__global__ void k_ee(const float* __restrict__ edge_emb,
                     const float* __restrict__ W_e,
                     const float* __restrict__ attn_e) {
    int t = threadIdx.x;
    if (t >= ET * HH) return;
    int et = t >> 2;
    int h  = t & 3;
    float acc = 0.f;
    for (int f = 0; f < EFF; f++) {
        const float* w = W_e + (h * EFF + f) * EFF;
        float emb = 0.f;
        #pragma unroll
        for (int g = 0; g < EFF; g++)
            emb += edge_emb[et * EFF + g] * w[g];
        acc += attn_e[h * EFF + f] * emb;
    }
    g_ee[et * HH + h] = acc;
}

// ---------------------------------------------------------------------------
// Kernel 1: per-node. One warp per node.
//   fs computed in fp32 (exact el/er scores), stored bf16 for the gather.
// ---------------------------------------------------------------------------
__global__ void k_node(const float* __restrict__ feat,
                       const float* __restrict__ fc,
                       const float* __restrict__ attn_l,
                       const float* __restrict__ attn_r,
                       const int*   __restrict__ node_types) {
    int warp = (blockIdx.x * blockDim.x + threadIdx.x) >> 5;
    int lane = threadIdx.x & 31;
    if (warp >= NN) return;

    int nt = node_types[warp];
    float4 f  = __ldcs((const float4*)(feat + (size_t)warp * HD) + lane);
    float4 c  = ((const float4*)(fc   + nt * HD))[lane];
    float4 fs = make_float4(f.x * c.x, f.y * c.y, f.z * c.z, f.w * c.w);

    // pack 4 bf16 into 8 bytes
    __nv_bfloat162 lo = __floats2bfloat162_rn(fs.x, fs.y);
    __nv_bfloat162 hi = __floats2bfloat162_rn(fs.z, fs.w);
    uint2 packed;
    packed.x = *reinterpret_cast<unsigned int*>(&lo);
    packed.y = *reinterpret_cast<unsigned int*>(&hi);
    ((uint2*)(g_fsh + (size_t)warp * HD))[lane] = packed;

    float4 al = ((const float4*)attn_l)[lane];
    float4 ar = ((const float4*)attn_r)[lane];
    float el = fs.x * al.x + fs.y * al.y + fs.z * al.z + fs.w * al.w;
    float er = fs.x * ar.x + fs.y * ar.y + fs.z * ar.z + fs.w * ar.w;

    #pragma unroll
    for (int off = 4; off >= 1; off >>= 1) {
        el += __shfl_down_sync(0xffffffffu, el, off);
        er += __shfl_down_sync(0xffffffffu, er, off);
    }
    int h = lane >> 3;
    if ((lane & 7) == 0) {
        g_el[warp * HH + h] = el;
        g_er[warp * HH + h] = er;
    }
    if (lane < HH) g_s[warp * HH + lane] = 0.f;
    if (lane == 4) g_deg[warp] = 0;
}

// ---------------------------------------------------------------------------
// Kernel 2: per-edge scores + dst histogram. One thread per edge.
// ---------------------------------------------------------------------------
__global__ void k_score(const int* __restrict__ src,
                        const int* __restrict__ dst,
                        const int* __restrict__ e_feat) {
    int e = blockIdx.x * blockDim.x + threadIdx.x;
    if (e >= EE) return;
    int s = src[e], d = dst[e], t = e_feat[e];

    float4 el = ((const float4*)g_el)[s];
    float4 er = ((const float4*)g_er)[d];
    float4 ee = ((const float4*)g_ee)[t];

    float v0 = el.x + er.x + ee.x;
    float v1 = el.y + er.y + ee.y;
    float v2 = el.z + er.z + ee.z;
    float v3 = el.w + er.w + ee.w;
    v0 = v0 > 0.f ? v0 : NEG_SLOPE * v0;
    v1 = v1 > 0.f ? v1 : NEG_SLOPE * v1;
    v2 = v2 > 0.f ? v2 : NEG_SLOPE * v2;
    v3 = v3 > 0.f ? v3 : NEG_SLOPE * v3;

    float4 ex = make_float4(__expf(v0), __expf(v1), __expf(v2), __expf(v3));
    __stcs((float4*)g_ex + e, ex);

    float* sp = g_s + d * HH;
    asm volatile("red.global.add.v4.f32 [%0], {%1, %2, %3, %4};"
                 :: "l"(sp), "f"(ex.x), "f"(ex.y), "f"(ex.z), "f"(ex.w)
                 : "memory");
    atomicAdd(&g_deg[d], 1);
}

// ---------------------------------------------------------------------------
// Kernel 3a: per-block exclusive scan of g_deg.
// ---------------------------------------------------------------------------
__global__ void k_scan_local() {
    __shared__ int warp_sums[32];
    int tid = threadIdx.x, lane = tid & 31, wid = tid >> 5;
    int i = blockIdx.x * SCAN_BLK + tid;
    int v = (i < NN) ? g_deg[i] : 0;
    int x = v;
    #pragma unroll
    for (int off = 1; off < 32; off <<= 1) {
        int y = __shfl_up_sync(0xffffffffu, x, off);
        if (lane >= off) x += y;
    }
    if (lane == 31) warp_sums[wid] = x;
    __syncthreads();
    if (wid == 0) {
        int w = warp_sums[lane];
        #pragma unroll
        for (int off = 1; off < 32; off <<= 1) {
            int y = __shfl_up_sync(0xffffffffu, w, off);
            if (lane >= off) w += y;
        }
        warp_sums[lane] = w;
    }
    __syncthreads();
    int excl = (wid ? warp_sums[wid - 1] : 0) + x - v;
    if (i < NN) g_rowptr[i] = excl;
    if (tid == SCAN_BLK - 1) g_bsum[blockIdx.x] = excl + v;
}

// ---------------------------------------------------------------------------
// Kernel 3b: scan the block totals.
// ---------------------------------------------------------------------------
__global__ void k_scan_bsum() {
    __shared__ int warp_sums[4];
    int tid = threadIdx.x, lane = tid & 31, wid = tid >> 5;   // 128 threads
    int v = (tid < SCAN_NB) ? g_bsum[tid] : 0;
    int x = v;
    #pragma unroll
    for (int off = 1; off < 32; off <<= 1) {
        int y = __shfl_up_sync(0xffffffffu, x, off);
        if (lane >= off) x += y;
    }
    if (lane == 31) warp_sums[wid] = x;
    __syncthreads();
    int carry = 0;
    for (int w = 0; w < wid; w++) carry += warp_sums[w];
    if (tid < SCAN_NB) g_boff[tid] = carry + x - v;
    if (tid == SCAN_NB - 1) g_rowptr[NN] = carry + x;
}

// ---------------------------------------------------------------------------
// Kernel 3c: add block offsets; init cursors.
// ---------------------------------------------------------------------------
__global__ void k_scan_add() {
    int i = blockIdx.x * SCAN_BLK + threadIdx.x;
    if (i >= NN) return;
    int r = g_rowptr[i] + g_boff[blockIdx.x];
    g_rowptr[i] = r;
    g_cursor[i] = r;
}

// ---------------------------------------------------------------------------
// Kernel 4: scatter edges into dst-sorted order. One thread per edge.
// ---------------------------------------------------------------------------
__global__ void k_scatter(const int* __restrict__ src,
                          const int* __restrict__ dst,
                          float* __restrict__ out) {
    int e = blockIdx.x * blockDim.x + threadIdx.x;
    if (e >= EE) return;
    int s = src[e], d = dst[e];

    float4 ex = __ldcs((const float4*)g_ex + e);
    float4 sv = ((const float4*)g_s)[d];
    float4 a  = make_float4(ex.x / sv.x, ex.y / sv.y, ex.z / sv.z, ex.w / sv.w);

    __stcs((float4*)(out + (size_t)NN * HD) + e, a);   // a output, coalesced

    int pos = atomicAdd(&g_cursor[d], 1);
    __stcs(&g_srcs[pos], s);
    __stcs((float4*)g_asrt + pos, a);
}

// ---------------------------------------------------------------------------
// Kernel 5: gather-side aggregation. One warp per dst node; atomic-free.
//   fs gathered in bf16 (8B/lane); streaming hints on read-once arrays.
// ---------------------------------------------------------------------------
__global__ void __launch_bounds__(256) k_agg(const float* __restrict__ feat,
                                             float* __restrict__ out) {
    int warp = (blockIdx.x * blockDim.x + threadIdx.x) >> 5;
    int lane = threadIdx.x & 31;
    if (warp >= NN) return;

    int beg = g_rowptr[warp];
    int end = g_rowptr[warp + 1];
    int h = lane >> 3;

    float accx = 0.f, accy = 0.f, accz = 0.f, accw = 0.f;
    #pragma unroll 4
    for (int j = beg; j < end; j++) {
        int   s = __ldcs(&g_srcs[j]);
        float a = __ldcs(&g_asrt[j * HH + h]);
        uint2 p = __ldg((const uint2*)(g_fsh + (size_t)s * HD) + lane);
        __nv_bfloat162 lo = *reinterpret_cast<__nv_bfloat162*>(&p.x);
        __nv_bfloat162 hi = *reinterpret_cast<__nv_bfloat162*>(&p.y);
        float2 flo = __bfloat1622float2(lo);
        float2 fhi = __bfloat1622float2(hi);
        accx += flo.x * a;
        accy += flo.y * a;
        accz += fhi.x * a;
        accw += fhi.y * a;
    }

    float4 f = __ldcs((const float4*)(feat + (size_t)warp * HD) + lane);
    float4 r = make_float4(f.x + accx, f.y + accy, f.z + accz, f.w + accw);
    __stcs((float4*)(out + (size_t)warp * HD) + lane, r);
}

// ---------------------------------------------------------------------------
extern "C" void kernel_launch(void* const* d_in, const int* in_sizes, int n_in,
                              void* d_out, int out_size) {
    const float* feat       = (const float*)d_in[0];
    const float* fc         = (const float*)d_in[1];
    const float* edge_emb   = (const float*)d_in[2];
    const float* W_e        = (const float*)d_in[3];
    const float* attn_l     = (const float*)d_in[4];
    const float* attn_r     = (const float*)d_in[5];
    const float* attn_e     = (const float*)d_in[6];
    const int*   node_types = (const int*)d_in[7];
    const int*   e_feat     = (const int*)d_in[8];
    const int*   src        = (const int*)d_in[9];
    const int*   dst        = (const int*)d_in[10];
    float* out = (float*)d_out;

    k_ee<<<1, 32>>>(edge_emb, W_e, attn_e);

    int node_blocks = (NN + 7) / 8;            // warp per node
    k_node<<<node_blocks, 256>>>(feat, fc, attn_l, attn_r, node_types);

    int score_blocks = (EE + 255) / 256;
    k_score<<<score_blocks, 256>>>(src, dst, e_feat);

    k_scan_local<<<SCAN_NB, SCAN_BLK>>>();
    k_scan_bsum<<<1, 128>>>();
    k_scan_add<<<SCAN_NB, SCAN_BLK>>>();

    k_scatter<<<score_blocks, 256>>>(src, dst, out);

    int agg_blocks = (NN + 7) / 8;             // warp per dst node
    k_agg<<<agg_blocks, 256>>>(feat, out);
}